// round 1
// baseline (speedup 1.0000x reference)
#include <cuda_runtime.h>

// ---------------------------------------------------------------------------
// Criss-cross attention block, fp32 staged pipeline.
// B=8, C=256, CQ=32, H=W=128.
// ---------------------------------------------------------------------------

#define Bn 8
#define Cc 256
#define CQn 32
#define Hh 128
#define Wn 128
#define HWn (Hh*Wn)

// Scratch (static device arrays; no runtime allocation).
__device__ float g_q_hw[Bn*HWn*CQn];       // [b][h][w][o]
__device__ float g_q_wh[Bn*HWn*CQn];       // [b][w][h][o]
__device__ float g_k_hw[Bn*HWn*CQn];       // [b][h][w][o]
__device__ float g_k_wh[Bn*HWn*CQn];       // [b][w][h][o]
__device__ float g_v_hwc[Bn*HWn*Cc];       // [b][h][w][c]
__device__ float g_v_whc[Bn*HWn*Cc];       // [b][w][h][c]
__device__ float g_eH[Bn*Wn*Hh*Hh];        // [b][w][h][g]   (g over H)
__device__ float g_eW[Bn*Hh*Wn*Wn];        // [b][h][w][g]   (g over W)
__device__ float g_oH[Bn*HWn*Cc];          // [b][w][h][c]
__device__ float g_oW[Bn*HWn*Cc];          // [b][h][w][c]

__device__ __forceinline__ float neg_inf_f() { return __int_as_float(0xff800000); }

// ---------------------------------------------------------------------------
// Kernel 1: fused QKV projection.
// Out(320 x 16384) = [Wq;Wk;Wv](320x256) @ X_b(256x16384) + bias.
// grid: (256 n-tiles, 5 m-tiles, B), block 256, 64x64 tile, 4x4 per thread.
// ---------------------------------------------------------------------------
__global__ __launch_bounds__(256) void proj_kernel(
    const float* __restrict__ x,
    const float* __restrict__ Wq, const float* __restrict__ bq,
    const float* __restrict__ Wk, const float* __restrict__ bk,
    const float* __restrict__ Wv, const float* __restrict__ bv)
{
    __shared__ float As[16][64];   // As[k][m]
    __shared__ float Bs[16][64];   // Bs[k][n]

    const int b  = blockIdx.z;
    const int mt = blockIdx.y;
    const int n0 = blockIdx.x * 64;
    const int t  = threadIdx.x;
    const int tx = t & 15, ty = t >> 4;

    // A loader: thread loads one float4 per k-chunk from its assigned row.
    const int arow = t >> 2;         // 0..63
    const int afq  = (t & 3) * 4;    // 0,4,8,12
    const int r    = mt * 64 + arow; // global output row in [0,320)
    const float* Arow;
    if      (r < 32) Arow = Wq + r * Cc;
    else if (r < 64) Arow = Wk + (r - 32) * Cc;
    else             Arow = Wv + (r - 64) * Cc;

    // B loader
    const int bkk = t >> 4;          // 0..15
    const int bnq = (t & 15) * 4;
    const float* Xb = x + (size_t)b * Cc * HWn;

    float acc[4][4];
    #pragma unroll
    for (int i = 0; i < 4; i++)
        #pragma unroll
        for (int j = 0; j < 4; j++) acc[i][j] = 0.f;

    for (int kc = 0; kc < Cc; kc += 16) {
        float4 av = *reinterpret_cast<const float4*>(Arow + kc + afq);
        float4 xv = *reinterpret_cast<const float4*>(Xb + (size_t)(kc + bkk) * HWn + n0 + bnq);
        __syncthreads();
        As[afq + 0][arow] = av.x;
        As[afq + 1][arow] = av.y;
        As[afq + 2][arow] = av.z;
        As[afq + 3][arow] = av.w;
        *reinterpret_cast<float4*>(&Bs[bkk][bnq]) = xv;
        __syncthreads();
        #pragma unroll
        for (int kk = 0; kk < 16; kk++) {
            float a0 = As[kk][ty * 4 + 0];
            float a1 = As[kk][ty * 4 + 1];
            float a2 = As[kk][ty * 4 + 2];
            float a3 = As[kk][ty * 4 + 3];
            float4 bb = *reinterpret_cast<float4*>(&Bs[kk][tx * 4]);
            acc[0][0] += a0 * bb.x; acc[0][1] += a0 * bb.y; acc[0][2] += a0 * bb.z; acc[0][3] += a0 * bb.w;
            acc[1][0] += a1 * bb.x; acc[1][1] += a1 * bb.y; acc[1][2] += a1 * bb.z; acc[1][3] += a1 * bb.w;
            acc[2][0] += a2 * bb.x; acc[2][1] += a2 * bb.y; acc[2][2] += a2 * bb.z; acc[2][3] += a2 * bb.w;
            acc[3][0] += a3 * bb.x; acc[3][1] += a3 * bb.y; acc[3][2] += a3 * bb.z; acc[3][3] += a3 * bb.w;
        }
    }

    // Epilogue: bias + scatter into channel-last dual layouts.
    #pragma unroll
    for (int i = 0; i < 4; i++) {
        const int rr = mt * 64 + ty * 4 + i;
        int o; float bias; int which;   // 0=q,1=k,2=v
        if (rr < 32)      { o = rr;      bias = bq[o]; which = 0; }
        else if (rr < 64) { o = rr - 32; bias = bk[o]; which = 1; }
        else              { o = rr - 64; bias = bv[o]; which = 2; }
        #pragma unroll
        for (int j = 0; j < 4; j++) {
            const int p = n0 + tx * 4 + j;
            const int h = p >> 7, w = p & 127;
            const float val = acc[i][j] + bias;
            const size_t idx_hw = (size_t)(b * Hh + h) * Wn + w;
            const size_t idx_wh = (size_t)(b * Wn + w) * Hh + h;
            if (which == 0)      { g_q_hw[idx_hw * CQn + o] = val; g_q_wh[idx_wh * CQn + o] = val; }
            else if (which == 1) { g_k_hw[idx_hw * CQn + o] = val; g_k_wh[idx_wh * CQn + o] = val; }
            else                 { g_v_hwc[idx_hw * Cc + o] = val; g_v_whc[idx_wh * Cc + o] = val; }
        }
    }
}

// ---------------------------------------------------------------------------
// Kernel 2/3: score GEMMs. 128x128x32 per block.
// ISH=true : per (b,w): eH[h][g] = Q_wh(h,:) . K_wh(g,:)   (diag h==g -> -inf)
// ISH=false: per (b,h): eW[w][g] = Q_hw(w,:) . K_hw(g,:)
// grid: B*128 blocks, block 256 threads, 8x8 per thread.
// ---------------------------------------------------------------------------
template <bool ISH>
__global__ __launch_bounds__(256) void score_kernel()
{
    __shared__ float Qs[128][32];
    __shared__ float Ks[32][132];   // transposed, padded

    const int bs = blockIdx.x;      // b*128 + (w or h)
    const int t  = threadIdx.x;
    const float* Q = (ISH ? g_q_wh : g_q_hw) + (size_t)bs * 128 * CQn;
    const float* K = (ISH ? g_k_wh : g_k_hw) + (size_t)bs * 128 * CQn;
    float* O       = (ISH ? g_eH   : g_eW)   + (size_t)bs * 128 * 128;

    #pragma unroll
    for (int q = 0; q < 4; q++) {
        const int idx = q * 256 + t;        // 0..1023 float4 slots
        const int row = idx >> 3;           // 0..127
        const int oq  = (idx & 7) * 4;      // 0..28
        float4 qv = *reinterpret_cast<const float4*>(Q + row * CQn + oq);
        *reinterpret_cast<float4*>(&Qs[row][oq]) = qv;
        float4 kv = *reinterpret_cast<const float4*>(K + row * CQn + oq);
        Ks[oq + 0][row] = kv.x;
        Ks[oq + 1][row] = kv.y;
        Ks[oq + 2][row] = kv.z;
        Ks[oq + 3][row] = kv.w;
    }
    __syncthreads();

    const int tx = t & 15, ty = t >> 4;
    const int h0 = ty * 8, g0 = tx * 8;
    float acc[8][8];
    #pragma unroll
    for (int i = 0; i < 8; i++)
        #pragma unroll
        for (int j = 0; j < 8; j++) acc[i][j] = 0.f;

    #pragma unroll
    for (int o = 0; o < 32; o++) {
        float a[8];
        #pragma unroll
        for (int i = 0; i < 8; i++) a[i] = Qs[h0 + i][o];
        float4 b0 = *reinterpret_cast<float4*>(&Ks[o][g0]);
        float4 b1 = *reinterpret_cast<float4*>(&Ks[o][g0 + 4]);
        float bb[8] = {b0.x, b0.y, b0.z, b0.w, b1.x, b1.y, b1.z, b1.w};
        #pragma unroll
        for (int i = 0; i < 8; i++)
            #pragma unroll
            for (int j = 0; j < 8; j++)
                acc[i][j] += a[i] * bb[j];
    }

    #pragma unroll
    for (int i = 0; i < 8; i++) {
        const int h = h0 + i;
        float vals[8];
        #pragma unroll
        for (int j = 0; j < 8; j++) {
            vals[j] = acc[i][j];
            if (ISH && (g0 + j == h)) vals[j] = neg_inf_f();
        }
        float4 r0 = {vals[0], vals[1], vals[2], vals[3]};
        float4 r1 = {vals[4], vals[5], vals[6], vals[7]};
        *reinterpret_cast<float4*>(O + h * 128 + g0)     = r0;
        *reinterpret_cast<float4*>(O + h * 128 + g0 + 4) = r1;
    }
}

// ---------------------------------------------------------------------------
// Kernel 4: joint softmax over 256 concat scores, one warp per pixel, in place.
// grid: B*H*W/8 blocks of 256 threads (8 warps).
// ---------------------------------------------------------------------------
__global__ __launch_bounds__(256) void softmax_kernel()
{
    const int wid  = blockIdx.x * 8 + (threadIdx.x >> 5);
    const int lane = threadIdx.x & 31;
    const int b  = wid >> 14;
    const int hw = wid & 16383;
    const int h  = hw >> 7, w = hw & 127;

    float* pH = g_eH + ((size_t)(b * Wn + w) * Hh + h) * Hh;
    float* pW = g_eW + ((size_t)(b * Hh + h) * Wn + w) * Wn;

    float4 vh = *reinterpret_cast<float4*>(pH + lane * 4);
    float4 vw = *reinterpret_cast<float4*>(pW + lane * 4);

    float m = fmaxf(fmaxf(fmaxf(vh.x, vh.y), fmaxf(vh.z, vh.w)),
                    fmaxf(fmaxf(vw.x, vw.y), fmaxf(vw.z, vw.w)));
    #pragma unroll
    for (int off = 16; off; off >>= 1)
        m = fmaxf(m, __shfl_xor_sync(0xffffffffu, m, off));

    vh.x = __expf(vh.x - m); vh.y = __expf(vh.y - m);
    vh.z = __expf(vh.z - m); vh.w = __expf(vh.w - m);
    vw.x = __expf(vw.x - m); vw.y = __expf(vw.y - m);
    vw.z = __expf(vw.z - m); vw.w = __expf(vw.w - m);

    float s = vh.x + vh.y + vh.z + vh.w + vw.x + vw.y + vw.z + vw.w;
    #pragma unroll
    for (int off = 16; off; off >>= 1)
        s += __shfl_xor_sync(0xffffffffu, s, off);

    const float inv = 1.f / s;
    vh.x *= inv; vh.y *= inv; vh.z *= inv; vh.w *= inv;
    vw.x *= inv; vw.y *= inv; vw.z *= inv; vw.w *= inv;

    *reinterpret_cast<float4*>(pH + lane * 4) = vh;
    *reinterpret_cast<float4*>(pW + lane * 4) = vw;
}

// ---------------------------------------------------------------------------
// Kernel 5/6: output GEMMs, 128x128x128 per block.
// ISH=true : per (b,w): oH[h][c] = sum_g aH[h][g] * v_whc[g][c]
// ISH=false: per (b,h): oW[w][c] = sum_g aW[w][g] * v_hwc[g][c]
// grid: (2 c-halves, B*128), block 256, 8x8 per thread.
// ---------------------------------------------------------------------------
template <bool ISH>
__global__ __launch_bounds__(256) void out_kernel()
{
    __shared__ float As[16][132];   // As[g][h], padded
    __shared__ float Bs[16][132];   // Bs[g][c], padded

    const int bs = blockIdx.y;
    const int c0 = blockIdx.x * 128;
    const int t  = threadIdx.x;
    const float* A = (ISH ? g_eH   : g_eW)   + (size_t)bs * 128 * 128;
    const float* V = (ISH ? g_v_whc : g_v_hwc) + (size_t)bs * 128 * Cc;
    float* O       = (ISH ? g_oH   : g_oW)   + (size_t)bs * 128 * Cc;

    const int tx = t & 15, ty = t >> 4;
    const int h0 = ty * 8, cc0 = tx * 8;

    float acc[8][8];
    #pragma unroll
    for (int i = 0; i < 8; i++)
        #pragma unroll
        for (int j = 0; j < 8; j++) acc[i][j] = 0.f;

    for (int kc = 0; kc < 128; kc += 16) {
        float4 a4[2], b4[2];
        #pragma unroll
        for (int q = 0; q < 2; q++) {
            const int idx = q * 256 + t;        // 0..511
            const int ha  = idx >> 2;           // 0..127
            const int gq  = (idx & 3) * 4;      // 0,4,8,12
            a4[q] = *reinterpret_cast<const float4*>(A + ha * 128 + kc + gq);
            const int kk = idx >> 5;            // 0..15
            const int cq = (idx & 31) * 4;      // 0..124
            b4[q] = *reinterpret_cast<const float4*>(V + (size_t)(kc + kk) * Cc + c0 + cq);
        }
        __syncthreads();
        #pragma unroll
        for (int q = 0; q < 2; q++) {
            const int idx = q * 256 + t;
            const int ha  = idx >> 2;
            const int gq  = (idx & 3) * 4;
            As[gq + 0][ha] = a4[q].x;
            As[gq + 1][ha] = a4[q].y;
            As[gq + 2][ha] = a4[q].z;
            As[gq + 3][ha] = a4[q].w;
            const int kk = idx >> 5;
            const int cq = (idx & 31) * 4;
            *reinterpret_cast<float4*>(&Bs[kk][cq]) = b4[q];
        }
        __syncthreads();
        #pragma unroll
        for (int kk = 0; kk < 16; kk++) {
            float4 av0 = *reinterpret_cast<float4*>(&As[kk][h0]);
            float4 av1 = *reinterpret_cast<float4*>(&As[kk][h0 + 4]);
            float4 bv0 = *reinterpret_cast<float4*>(&Bs[kk][cc0]);
            float4 bv1 = *reinterpret_cast<float4*>(&Bs[kk][cc0 + 4]);
            float a[8] = {av0.x, av0.y, av0.z, av0.w, av1.x, av1.y, av1.z, av1.w};
            float bb[8] = {bv0.x, bv0.y, bv0.z, bv0.w, bv1.x, bv1.y, bv1.z, bv1.w};
            #pragma unroll
            for (int i = 0; i < 8; i++)
                #pragma unroll
                for (int j = 0; j < 8; j++)
                    acc[i][j] += a[i] * bb[j];
        }
        __syncthreads();
    }

    #pragma unroll
    for (int i = 0; i < 8; i++) {
        float* row = O + (size_t)(h0 + i) * Cc + c0 + cc0;
        float4 r0 = {acc[i][0], acc[i][1], acc[i][2], acc[i][3]};
        float4 r1 = {acc[i][4], acc[i][5], acc[i][6], acc[i][7]};
        *reinterpret_cast<float4*>(row)     = r0;
        *reinterpret_cast<float4*>(row + 4) = r1;
    }
}

// ---------------------------------------------------------------------------
// Kernel 7: out[b,c,h,w] = gamma*(oH[b,w,h,c] + oW[b,h,w,c]) + x[b,c,h,w].
// grid: (W/32, C/32, B*H), block 256; smem 32x32 transpose.
// ---------------------------------------------------------------------------
__global__ __launch_bounds__(256) void final_kernel(
    const float* __restrict__ x, const float* __restrict__ gamma,
    float* __restrict__ out)
{
    __shared__ float sm[32][33];
    const int bh = blockIdx.z;
    const int b = bh >> 7, h = bh & 127;
    const int c0 = blockIdx.y * 32;
    const int w0 = blockIdx.x * 32;
    const int t  = threadIdx.x;
    const float g = gamma[0];

    {
        const int wr = t >> 3;
        const int cq = (t & 7) * 4;
        const float4 a = *reinterpret_cast<const float4*>(
            g_oH + ((size_t)(b * Wn + (w0 + wr)) * Hh + h) * Cc + c0 + cq);
        const float4 bb = *reinterpret_cast<const float4*>(
            g_oW + ((size_t)(b * Hh + h) * Wn + (w0 + wr)) * Cc + c0 + cq);
        sm[wr][cq + 0] = a.x + bb.x;
        sm[wr][cq + 1] = a.y + bb.y;
        sm[wr][cq + 2] = a.z + bb.z;
        sm[wr][cq + 3] = a.w + bb.w;
    }
    __syncthreads();
    {
        const int cr = t >> 3;
        const int wq = (t & 7) * 4;
        const size_t oidx = ((size_t)(b * Cc + c0 + cr) * Hh + h) * Wn + w0 + wq;
        const float4 xr = *reinterpret_cast<const float4*>(x + oidx);
        float4 r;
        r.x = g * sm[wq + 0][cr] + xr.x;
        r.y = g * sm[wq + 1][cr] + xr.y;
        r.z = g * sm[wq + 2][cr] + xr.z;
        r.w = g * sm[wq + 3][cr] + xr.w;
        *reinterpret_cast<float4*>(out + oidx) = r;
    }
}

// ---------------------------------------------------------------------------
extern "C" void kernel_launch(void* const* d_in, const int* in_sizes, int n_in,
                              void* d_out, int out_size)
{
    const float* x     = (const float*)d_in[0];
    const float* Wq    = (const float*)d_in[1];
    const float* bq    = (const float*)d_in[2];
    const float* Wk    = (const float*)d_in[3];
    const float* bk    = (const float*)d_in[4];
    const float* Wv    = (const float*)d_in[5];
    const float* bv    = (const float*)d_in[6];
    const float* gamma = (const float*)d_in[7];
    float* out = (float*)d_out;

    proj_kernel<<<dim3(HWn / 64, 5, Bn), 256>>>(x, Wq, bq, Wk, bk, Wv, bv);

    score_kernel<true ><<<Bn * Wn, 256>>>();
    score_kernel<false><<<Bn * Hh, 256>>>();

    softmax_kernel<<<(Bn * HWn) / 8, 256>>>();

    out_kernel<true ><<<dim3(2, Bn * Wn), 256>>>();
    out_kernel<false><<<dim3(2, Bn * Hh), 256>>>();

    final_kernel<<<dim3(Wn / 32, Cc / 32, Bn * Hh), 256>>>(x, gamma, out);
}